// round 2
// baseline (speedup 1.0000x reference)
#include <cuda_runtime.h>

// KANLayer: out = basis(x) @ spline_weight + silu(x) @ base_w^T + base_b
// One virtual GEMM A(16384 x 4608) @ B(4608 x 512); A expanded on the fly:
// for input col i, virtual rows i*9+g are RBF basis (g<8) and silu (g==8).

#define N_ROWS  16384
#define IN_DIM  512
#define OUT_DIM 512
#define NG      8

// Tiling
#define BM  128
#define BN  64
#define ICB 4            // input columns per K-chunk (512/4 = 128 chunks)
#define BK  (ICB * 9)    // 36 virtual K rows per chunk
#define NTHREADS 256

#define SMEM_FLOATS (BK * BM + BK * BN)   // 36*128 + 36*64 = 6912 floats
#define SMEM_BYTES  (SMEM_FLOATS * 4)     // 27648 B  (< 48 KB, no opt-in needed)

// Scratch: transposed base_w, Wt[i][o] = base_w[o][i]  (1 MB static)
__device__ float g_Wt[IN_DIM * OUT_DIM];

__global__ void transpose_w_kernel(const float* __restrict__ w) {
    __shared__ float tile[32][33];
    int bx = blockIdx.x * 32;   // IN (i) block
    int by = blockIdx.y * 32;   // OUT (o) block
    int tx = threadIdx.x;       // 0..31
    int ty = threadIdx.y;       // 0..7
    #pragma unroll
    for (int j = 0; j < 32; j += 8)
        tile[ty + j][tx] = w[(by + ty + j) * IN_DIM + (bx + tx)];
    __syncthreads();
    #pragma unroll
    for (int j = 0; j < 32; j += 8)
        g_Wt[(bx + ty + j) * OUT_DIM + (by + tx)] = tile[tx][ty + j];
}

__global__ __launch_bounds__(NTHREADS)
void kan_kernel(const float* __restrict__ x,
                const float* __restrict__ grid,
                const float* __restrict__ sw,     // [IN_DIM*NG, OUT_DIM]
                const float* __restrict__ bb,     // [OUT_DIM]
                float* __restrict__ out) {
    __shared__ float smem[SMEM_FLOATS];
    float* sA = smem;                 // [BK][BM]  K-major
    float* sB = smem + BK * BM;       // [BK][BN]

    const int tid  = threadIdx.x;
    const int rm   = tid >> 4;        // 0..15  -> rows rm*8 .. rm*8+7
    const int cn   = tid & 15;        // 0..15  -> cols cn*4 .. cn*4+3
    const int row0 = blockIdx.y * BM;
    const int col0 = blockIdx.x * BN;

    float gk[NG];
    #pragma unroll
    for (int g = 0; g < NG; g++) gk[g] = grid[g];
    const float inv_h = 7.0f / 4.0f;  // 1/h, h = 4/7

    float acc[8][4];
    #pragma unroll
    for (int r = 0; r < 8; r++)
        #pragma unroll
        for (int c = 0; c < 4; c++) acc[r][c] = 0.0f;

    // x staging: each thread expands 2 x-values: row xr = tid>>1, cols {xc, xc+1}? No:
    // 256 threads * 2 values = 512 = BM*ICB. Thread t: row = t >> 1, cols = (t&1)*2 + {0,1}
    const int xr = tid >> 1;
    const int xc = (tid & 1) * 2;
    // B staging: col bc = tid&63, k rows kb + 4*m (m=0..8)
    const int bc = tid & 63;
    const int kb = tid >> 6;

    for (int ic0 = 0; ic0 < IN_DIM; ic0 += ICB) {
        // ---- stage global loads into registers (before the barrier) ----
        float2 xv = *reinterpret_cast<const float2*>(
            &x[(row0 + xr) * IN_DIM + ic0 + xc]);

        float bv[BK / 4];
        #pragma unroll
        for (int m = 0; m < BK / 4; m++) {
            int k = kb + 4 * m;
            int g = k % 9;
            int i = ic0 + k / 9;
            if (g < 8)
                bv[m] = sw[(i * NG + g) * OUT_DIM + col0 + bc];
            else
                bv[m] = g_Wt[i * OUT_DIM + col0 + bc];
        }

        __syncthreads();   // previous chunk's smem reads complete

        // ---- expand x into sA (basis + silu), K-major ----
        float xs[2] = {xv.x, xv.y};
        #pragma unroll
        for (int j = 0; j < 2; j++) {
            float v = xs[j];
            int kbase = (xc + j) * 9;
            #pragma unroll
            for (int g = 0; g < NG; g++) {
                float t = (v - gk[g]) * inv_h;
                sA[(kbase + g) * BM + xr] = __expf(-t * t);
            }
            sA[(kbase + 8) * BM + xr] = v / (1.0f + __expf(-v));  // silu
        }
        #pragma unroll
        for (int m = 0; m < BK / 4; m++)
            sB[(kb + 4 * m) * BN + bc] = bv[m];

        __syncthreads();

        // ---- FFMA mainloop over this K-chunk ----
        #pragma unroll 4
        for (int k = 0; k < BK; k++) {
            float4 b4 = *reinterpret_cast<float4*>(&sB[k * BN + cn * 4]);
            float4 a0 = *reinterpret_cast<float4*>(&sA[k * BM + rm * 8]);
            float4 a1 = *reinterpret_cast<float4*>(&sA[k * BM + rm * 8 + 4]);
            float a[8] = {a0.x, a0.y, a0.z, a0.w, a1.x, a1.y, a1.z, a1.w};
            float b[4] = {b4.x, b4.y, b4.z, b4.w};
            #pragma unroll
            for (int r = 0; r < 8; r++)
                #pragma unroll
                for (int c = 0; c < 4; c++)
                    acc[r][c] += a[r] * b[c];
        }
    }

    // ---- epilogue: add bias, write float4 ----
    float4 bias = *reinterpret_cast<const float4*>(&bb[col0 + cn * 4]);
    #pragma unroll
    for (int r = 0; r < 8; r++) {
        int orow = row0 + rm * 8 + r;
        float4 o;
        o.x = acc[r][0] + bias.x;
        o.y = acc[r][1] + bias.y;
        o.z = acc[r][2] + bias.z;
        o.w = acc[r][3] + bias.w;
        *reinterpret_cast<float4*>(&out[orow * OUT_DIM + col0 + cn * 4]) = o;
    }
}

extern "C" void kernel_launch(void* const* d_in, const int* in_sizes, int n_in,
                              void* d_out, int out_size) {
    const float* x    = (const float*)d_in[0];
    const float* grid = (const float*)d_in[1];
    const float* sw   = (const float*)d_in[2];
    const float* bw   = (const float*)d_in[3];
    const float* bb   = (const float*)d_in[4];
    float* out = (float*)d_out;

    transpose_w_kernel<<<dim3(IN_DIM / 32, OUT_DIM / 32), dim3(32, 8)>>>(bw);

    dim3 gridDim(OUT_DIM / BN, N_ROWS / BM);
    kan_kernel<<<gridDim, NTHREADS>>>(x, grid, sw, bb, out);
}

// round 5
// speedup vs baseline: 1.3841x; 1.3841x over previous
#include <cuda_runtime.h>
#include <cuda_bf16.h>
#include <cstdint>

// ===========================================================================
// KANLayer via mma.sync (HMMA) bf16 split-precision GEMM (no 'a'-target PTX).
// out[n,o] = sum_k Avirt[n,k]*Bt[o,k] + bias[o],  K = 4608 virtual:
//   k = g*512 + i (g<8): Avirt = exp(-((x[n,i]-grid[g])*1.75)^2), Bt = spline_weight[i*8+g, o]
//   k = 4096 + i:        Avirt = silu(x[n,i]),                    Bt = base_w[o, i]
// 3-pass split: D = Ahi*Bhi + Ahi*Blo + Alo*Bhi  (fp32 accumulators)
// ===========================================================================

#define N_ROWS  16384
#define IN_DIM  512
#define OUT_DIM 512
#define KTOT    4608
#define KC      64
#define NCHUNK  72
#define BM      128
#define BN      128
#define NTHREADS 256

// per-stage smem: Ahi,Alo,Bhi,Blo each 128x64 bf16 = 16KB -> 64KB; 2 stages
#define STAGE_BYTES  65536
#define A_HI_OFF(s)  ((s) * STAGE_BYTES + 0)
#define A_LO_OFF(s)  ((s) * STAGE_BYTES + 16384)
#define B_HI_OFF(s)  ((s) * STAGE_BYTES + 32768)
#define B_LO_OFF(s)  ((s) * STAGE_BYTES + 49152)
#define SMEM_TOTAL   (2 * STAGE_BYTES)

// Pre-converted B: Bt_hi/lo[o][k]  (bf16, k contiguous)
__device__ __nv_bfloat16 g_Bt_hi[OUT_DIM * KTOT];
__device__ __nv_bfloat16 g_Bt_lo[OUT_DIM * KTOT];

// ---------------- helpers ----------------
__device__ __forceinline__ uint32_t smem_u32(const void* p) {
    uint32_t a;
    asm("{ .reg .u64 t; cvta.to.shared.u64 t, %1; cvt.u32.u64 %0, t; }" : "=r"(a) : "l"(p));
    return a;
}
// SW128 swizzle for 128B rows: XOR col bits [4:6] with row bits [0:2]
__device__ __forceinline__ uint32_t swaddr(uint32_t base, int row, int colb) {
    return base + row * 128 + (colb ^ ((row & 7) << 4));
}
__device__ __forceinline__ void ldsm4(uint32_t r[4], uint32_t addr) {
    asm volatile("ldmatrix.sync.aligned.m8n8.x4.shared.b16 {%0,%1,%2,%3}, [%4];"
                 : "=r"(r[0]), "=r"(r[1]), "=r"(r[2]), "=r"(r[3]) : "r"(addr));
}
__device__ __forceinline__ void mma16816(float c[4], const uint32_t a[4],
                                         uint32_t b0, uint32_t b1) {
    asm volatile(
        "mma.sync.aligned.m16n8k16.row.col.f32.bf16.bf16.f32 "
        "{%0,%1,%2,%3}, {%4,%5,%6,%7}, {%8,%9}, {%0,%1,%2,%3};"
        : "+f"(c[0]), "+f"(c[1]), "+f"(c[2]), "+f"(c[3])
        : "r"(a[0]), "r"(a[1]), "r"(a[2]), "r"(a[3]), "r"(b0), "r"(b1));
}
__device__ __forceinline__ void split_bf16(float v, uint16_t& hi, uint16_t& lo) {
    __nv_bfloat16 h = __float2bfloat16(v);
    float r = v - __bfloat162float(h);
    __nv_bfloat16 l = __float2bfloat16(r);
    hi = __bfloat16_as_ushort(h);
    lo = __bfloat16_as_ushort(l);
}
__device__ __forceinline__ void sts128(uint32_t addr, uint4 v) {
    asm volatile("st.shared.v4.b32 [%0], {%1,%2,%3,%4};"
                 :: "r"(addr), "r"(v.x), "r"(v.y), "r"(v.z), "r"(v.w) : "memory");
}
__device__ __forceinline__ void sts32(uint32_t addr, uint32_t v) {
    asm volatile("st.shared.b32 [%0], %1;" :: "r"(addr), "r"(v) : "memory");
}

// ---------------- pre-pass: build Bt_hi/lo ----------------
__global__ void convert_b_kernel(const float* __restrict__ sw,
                                 const float* __restrict__ bw) {
    __shared__ float tile[32][33];
    int g  = blockIdx.z;
    int i0 = blockIdx.x * 32, o0 = blockIdx.y * 32;
    int tx = threadIdx.x, ty = threadIdx.y;   // (32, 8)
    if (g < 8) {
        #pragma unroll
        for (int j = 0; j < 32; j += 8)
            tile[ty + j][tx] = sw[((size_t)(i0 + ty + j) * 8 + g) * OUT_DIM + o0 + tx];
        __syncthreads();
        #pragma unroll
        for (int j = 0; j < 32; j += 8) {
            float v = tile[tx][ty + j];
            int o = o0 + ty + j, i = i0 + tx;
            uint16_t h, l; split_bf16(v, h, l);
            size_t idx = (size_t)o * KTOT + g * IN_DIM + i;
            g_Bt_hi[idx] = __ushort_as_bfloat16(h);
            g_Bt_lo[idx] = __ushort_as_bfloat16(l);
        }
    } else {
        #pragma unroll
        for (int j = 0; j < 32; j += 8) {
            int o = o0 + ty + j, i = i0 + tx;
            float v = bw[(size_t)o * IN_DIM + i];
            uint16_t h, l; split_bf16(v, h, l);
            size_t idx = (size_t)o * KTOT + 4096 + i;
            g_Bt_hi[idx] = __ushort_as_bfloat16(h);
            g_Bt_lo[idx] = __ushort_as_bfloat16(l);
        }
    }
}

// ---------------- chunk fill helpers ----------------
__device__ __forceinline__ void fill_B(uint32_t sb, int stage, int chunk,
                                       int n0, int tid) {
    int brow = tid >> 1, bhalf = tid & 1;
    size_t goff = (size_t)(n0 + brow) * KTOT + (size_t)chunk * KC + bhalf * 32;
    const uint4* ph = reinterpret_cast<const uint4*>(g_Bt_hi + goff);
    const uint4* pl = reinterpret_cast<const uint4*>(g_Bt_lo + goff);
    uint32_t bh = sb + B_HI_OFF(stage);
    uint32_t bl = sb + B_LO_OFF(stage);
    #pragma unroll
    for (int j = 0; j < 4; j++)
        sts128(swaddr(bh, brow, bhalf * 64 + j * 16), ph[j]);
    #pragma unroll
    for (int j = 0; j < 4; j++)
        sts128(swaddr(bl, brow, bhalf * 64 + j * 16), pl[j]);
}

__device__ __forceinline__ void load_x(const float* __restrict__ x, int row0,
                                       int chunk, int am, int ah, float xs[32]) {
    int ic0 = (chunk & 7) * KC;
    const float4* xp = reinterpret_cast<const float4*>(
        x + (size_t)(row0 + am) * IN_DIM + ic0 + ah * 32);
    #pragma unroll
    for (int j = 0; j < 8; j++) {
        float4 v = xp[j];
        xs[4 * j] = v.x; xs[4 * j + 1] = v.y; xs[4 * j + 2] = v.z; xs[4 * j + 3] = v.w;
    }
}

__device__ __forceinline__ void fill_A(uint32_t sb, int stage, int chunk,
                                       const float* __restrict__ grid,
                                       int am, int ah, const float xs[32]) {
    const bool is_silu = (chunk >= 64);
    const float gv = is_silu ? 0.0f : __ldg(grid + (chunk >> 3));
    uint32_t ahb = sb + A_HI_OFF(stage);
    uint32_t alb = sb + A_LO_OFF(stage);
    #pragma unroll
    for (int p = 0; p < 16; p++) {
        float v0 = xs[2 * p], v1 = xs[2 * p + 1];
        float e0, e1;
        if (!is_silu) {
            float t0 = (v0 - gv) * 1.75f;
            float t1 = (v1 - gv) * 1.75f;
            e0 = __expf(-t0 * t0);
            e1 = __expf(-t1 * t1);
        } else {
            e0 = v0 / (1.0f + __expf(-v0));
            e1 = v1 / (1.0f + __expf(-v1));
        }
        uint16_t h0, l0, h1, l1;
        split_bf16(e0, h0, l0);
        split_bf16(e1, h1, l1);
        uint32_t hp = ((uint32_t)h1 << 16) | h0;
        uint32_t lp = ((uint32_t)l1 << 16) | l0;
        int colb = ah * 64 + p * 4;
        sts32(swaddr(ahb, am, colb), hp);
        sts32(swaddr(alb, am, colb), lp);
    }
}

// ---------------- main kernel ----------------
__global__ void __launch_bounds__(NTHREADS, 1)
kan_mma_kernel(const float* __restrict__ x,
               const float* __restrict__ grid,
               const float* __restrict__ bb,
               float* __restrict__ out) {
    extern __shared__ char smem[];
    uint32_t sb = smem_u32(smem);
    const int tid = threadIdx.x;
    const int wid = tid >> 5;
    const int lid = tid & 31;
    const int wm  = wid & 1;    // m half (64 rows)
    const int wn  = wid >> 1;   // n quarter (32 cols)

    const int row0 = blockIdx.y * BM;
    const int n0   = blockIdx.x * BN;

    const int am = tid >> 1;    // A fill row
    const int ah = tid & 1;     // A fill k-half

    float acc[4][4][4];
    #pragma unroll
    for (int mt = 0; mt < 4; mt++)
        #pragma unroll
        for (int nt = 0; nt < 4; nt++)
            #pragma unroll
            for (int q = 0; q < 4; q++) acc[mt][nt][q] = 0.0f;

    // prologue: fill chunk 0 into stage 0
    {
        float xs[32];
        fill_B(sb, 0, 0, n0, tid);
        load_x(x, row0, 0, am, ah, xs);
        fill_A(sb, 0, 0, grid, am, ah, xs);
    }
    __syncthreads();

    for (int c = 0; c < NCHUNK; c++) {
        const int s = c & 1;
        const int nc = c + 1;
        float xs[32];
        if (nc < NCHUNK) {
            fill_B(sb, nc & 1, nc, n0, tid);     // LDG->STS (other buffer, safe)
            load_x(x, row0, nc, am, ah, xs);     // LDG into regs
        }

        // ---- MMA over stage s ----
        const uint32_t Ah = sb + A_HI_OFF(s), Al = sb + A_LO_OFF(s);
        const uint32_t Bh = sb + B_HI_OFF(s), Bl = sb + B_LO_OFF(s);
        #pragma unroll
        for (int ks = 0; ks < 4; ks++) {
            const int acolb = ks * 32 + ((lid >> 4) << 4);
            uint32_t ahf[4][4], alf[4][4];
            #pragma unroll
            for (int mt = 0; mt < 4; mt++) {
                int row = wm * 64 + mt * 16 + (lid & 15);
                ldsm4(ahf[mt], swaddr(Ah, row, acolb));
                ldsm4(alf[mt], swaddr(Al, row, acolb));
            }
            const int bno = (lid & 7) + ((lid >> 4) << 3);
            const int bcolb = ks * 32 + (((lid >> 3) & 1) << 4);
            uint32_t bhf[2][4], blf[2][4];
            #pragma unroll
            for (int p = 0; p < 2; p++) {
                int row = wn * 32 + p * 16 + bno;
                ldsm4(bhf[p], swaddr(Bh, row, bcolb));
                ldsm4(blf[p], swaddr(Bl, row, bcolb));
            }
            #pragma unroll
            for (int mt = 0; mt < 4; mt++) {
                #pragma unroll
                for (int nt = 0; nt < 4; nt++) {
                    uint32_t b0h = bhf[nt >> 1][(nt & 1) * 2];
                    uint32_t b1h = bhf[nt >> 1][(nt & 1) * 2 + 1];
                    uint32_t b0l = blf[nt >> 1][(nt & 1) * 2];
                    uint32_t b1l = blf[nt >> 1][(nt & 1) * 2 + 1];
                    mma16816(acc[mt][nt], ahf[mt], b0h, b1h);   // hi*hi
                    mma16816(acc[mt][nt], ahf[mt], b0l, b1l);   // hi*lo
                    mma16816(acc[mt][nt], alf[mt], b0h, b1h);   // lo*hi
                }
            }
        }

        if (nc < NCHUNK)
            fill_A(sb, nc & 1, nc, grid, am, ah, xs);   // expand + STS
        __syncthreads();
    }

    // ---- epilogue: bias + store ----
    #pragma unroll
    for (int mt = 0; mt < 4; mt++) {
        int row = row0 + wm * 64 + mt * 16 + (lid >> 2);
        #pragma unroll
        for (int nt = 0; nt < 4; nt++) {
            int col = n0 + wn * 32 + nt * 8 + (lid & 3) * 2;
            float2 bv = *reinterpret_cast<const float2*>(bb + col);
            float2 o0, o1;
            o0.x = acc[mt][nt][0] + bv.x;
            o0.y = acc[mt][nt][1] + bv.y;
            o1.x = acc[mt][nt][2] + bv.x;
            o1.y = acc[mt][nt][3] + bv.y;
            *reinterpret_cast<float2*>(out + (size_t)row * OUT_DIM + col) = o0;
            *reinterpret_cast<float2*>(out + (size_t)(row + 8) * OUT_DIM + col) = o1;
        }
    }
}

// ---------------- launch ----------------
extern "C" void kernel_launch(void* const* d_in, const int* in_sizes, int n_in,
                              void* d_out, int out_size) {
    const float* x    = (const float*)d_in[0];
    const float* grid = (const float*)d_in[1];
    const float* sw   = (const float*)d_in[2];
    const float* bw   = (const float*)d_in[3];
    const float* bb   = (const float*)d_in[4];
    float* out = (float*)d_out;

    convert_b_kernel<<<dim3(16, 16, 9), dim3(32, 8)>>>(sw, bw);

    cudaFuncSetAttribute(kan_mma_kernel, cudaFuncAttributeMaxDynamicSharedMemorySize,
                         SMEM_TOTAL);
    dim3 g(OUT_DIM / BN, N_ROWS / BM);   // (4, 128) = 512 CTAs
    kan_mma_kernel<<<g, NTHREADS, SMEM_TOTAL>>>(x, grid, bb, out);
}

// round 10
// speedup vs baseline: 1.8814x; 1.3593x over previous
#include <cuda_runtime.h>
#include <cuda_bf16.h>
#include <cstdint>

// ===========================================================================
// KANLayer via mma.sync (HMMA) bf16 split-precision GEMM.
// out[n,o] = sum_k Avirt[n,k]*Bt[o,k] + bias[o],  K = 4608 virtual:
//   k = g*512 + i (g<8): Avirt = exp(-((x[n,i]-grid[g])*1.75)^2), Bt = spline_weight[i*8+g, o]
//   k = 4096 + i:        Avirt = silu(x[n,i]),                    Bt = base_w[o, i]
// 3-pass split: D = Ahi*Bhi + Ahi*Blo + Alo*Bhi  (fp32 accumulators)
// R6: BN=64 + launch_bounds(256,2) -> 2 CTAs/SM; cp.async B fills;
//     chunk order (ib outer, g inner) so x regs are reused 9x.
// ===========================================================================

#define N_ROWS  16384
#define IN_DIM  512
#define OUT_DIM 512
#define KTOT    4608
#define KC      64
#define NCHUNK  72
#define BM      128
#define BN      64
#define NTHREADS 256

// per-stage smem: Ahi 16K, Alo 16K, Bhi 8K, Blo 8K = 48KB; 2 stages = 96KB
#define STAGE_BYTES  49152
#define A_HI_OFF(s)  ((s) * STAGE_BYTES + 0)
#define A_LO_OFF(s)  ((s) * STAGE_BYTES + 16384)
#define B_HI_OFF(s)  ((s) * STAGE_BYTES + 32768)
#define B_LO_OFF(s)  ((s) * STAGE_BYTES + 40960)
#define SMEM_TOTAL   (2 * STAGE_BYTES)

// Pre-converted B: Bt_hi/lo[o][k]  (bf16, k contiguous)
__device__ __nv_bfloat16 g_Bt_hi[OUT_DIM * KTOT];
__device__ __nv_bfloat16 g_Bt_lo[OUT_DIM * KTOT];

// ---------------- helpers ----------------
__device__ __forceinline__ uint32_t smem_u32(const void* p) {
    uint32_t a;
    asm("{ .reg .u64 t; cvta.to.shared.u64 t, %1; cvt.u32.u64 %0, t; }" : "=r"(a) : "l"(p));
    return a;
}
// SW128 swizzle for 128B rows
__device__ __forceinline__ uint32_t swaddr(uint32_t base, int row, int colb) {
    return base + row * 128 + (colb ^ ((row & 7) << 4));
}
__device__ __forceinline__ void ldsm4(uint32_t r[4], uint32_t addr) {
    asm volatile("ldmatrix.sync.aligned.m8n8.x4.shared.b16 {%0,%1,%2,%3}, [%4];"
                 : "=r"(r[0]), "=r"(r[1]), "=r"(r[2]), "=r"(r[3]) : "r"(addr));
}
__device__ __forceinline__ void mma16816(float c[4], const uint32_t a[4],
                                         uint32_t b0, uint32_t b1) {
    asm volatile(
        "mma.sync.aligned.m16n8k16.row.col.f32.bf16.bf16.f32 "
        "{%0,%1,%2,%3}, {%4,%5,%6,%7}, {%8,%9}, {%0,%1,%2,%3};"
        : "+f"(c[0]), "+f"(c[1]), "+f"(c[2]), "+f"(c[3])
        : "r"(a[0]), "r"(a[1]), "r"(a[2]), "r"(a[3]), "r"(b0), "r"(b1));
}
__device__ __forceinline__ void split_bf16(float v, uint16_t& hi, uint16_t& lo) {
    __nv_bfloat16 h = __float2bfloat16(v);
    float r = v - __bfloat162float(h);
    __nv_bfloat16 l = __float2bfloat16(r);
    hi = __bfloat16_as_ushort(h);
    lo = __bfloat16_as_ushort(l);
}
__device__ __forceinline__ void sts32(uint32_t addr, uint32_t v) {
    asm volatile("st.shared.b32 [%0], %1;" :: "r"(addr), "r"(v) : "memory");
}
__device__ __forceinline__ void cp16(uint32_t dst, const void* src) {
    asm volatile("cp.async.cg.shared.global [%0], [%1], 16;"
                 :: "r"(dst), "l"(src) : "memory");
}
#define CP_COMMIT() asm volatile("cp.async.commit_group;" ::: "memory")
#define CP_WAIT0()  asm volatile("cp.async.wait_group 0;" ::: "memory")

// ---------------- pre-pass: build Bt_hi/lo ----------------
__global__ void convert_b_kernel(const float* __restrict__ sw,
                                 const float* __restrict__ bw) {
    __shared__ float tile[32][33];
    int g  = blockIdx.z;
    int i0 = blockIdx.x * 32, o0 = blockIdx.y * 32;
    int tx = threadIdx.x, ty = threadIdx.y;   // (32, 8)
    if (g < 8) {
        #pragma unroll
        for (int j = 0; j < 32; j += 8)
            tile[ty + j][tx] = sw[((size_t)(i0 + ty + j) * 8 + g) * OUT_DIM + o0 + tx];
        __syncthreads();
        #pragma unroll
        for (int j = 0; j < 32; j += 8) {
            float v = tile[tx][ty + j];
            int o = o0 + ty + j, i = i0 + tx;
            uint16_t h, l; split_bf16(v, h, l);
            size_t idx = (size_t)o * KTOT + g * IN_DIM + i;
            g_Bt_hi[idx] = __ushort_as_bfloat16(h);
            g_Bt_lo[idx] = __ushort_as_bfloat16(l);
        }
    } else {
        #pragma unroll
        for (int j = 0; j < 32; j += 8) {
            int o = o0 + ty + j, i = i0 + tx;
            float v = bw[(size_t)o * IN_DIM + i];
            uint16_t h, l; split_bf16(v, h, l);
            size_t idx = (size_t)o * KTOT + 4096 + i;
            g_Bt_hi[idx] = __ushort_as_bfloat16(h);
            g_Bt_lo[idx] = __ushort_as_bfloat16(l);
        }
    }
}

// ---------------- chunk fill helpers ----------------
// B tile: 64 rows x 64 k (hi+lo), cp.async 16B units. 512 units/array.
__device__ __forceinline__ void fill_B_async(uint32_t sb, int stage, int kk,
                                             int n0, int tid) {
    uint32_t bh = sb + B_HI_OFF(stage);
    uint32_t bl = sb + B_LO_OFF(stage);
    #pragma unroll
    for (int u0 = 0; u0 < 2; u0++) {
        int u = tid + u0 * 256;
        int row = u >> 3, c16 = u & 7;
        size_t off = (size_t)(n0 + row) * KTOT + kk + c16 * 8;
        uint32_t d = swaddr(0, row, c16 * 16);
        cp16(bh + d, g_Bt_hi + off);
        cp16(bl + d, g_Bt_lo + off);
    }
}

__device__ __forceinline__ void load_x(const float* __restrict__ x, int row0,
                                       int ib, int am, int ah, float xs[32]) {
    const float4* xp = reinterpret_cast<const float4*>(
        x + (size_t)(row0 + am) * IN_DIM + ib * KC + ah * 32);
    #pragma unroll
    for (int j = 0; j < 8; j++) {
        float4 v = xp[j];
        xs[4 * j] = v.x; xs[4 * j + 1] = v.y; xs[4 * j + 2] = v.z; xs[4 * j + 3] = v.w;
    }
}

__device__ __forceinline__ void fill_A(uint32_t sb, int stage, int gg,
                                       const float* __restrict__ grid,
                                       int am, int ah, const float xs[32]) {
    const bool is_silu = (gg == 8);
    const float gv = is_silu ? 0.0f : __ldg(grid + gg);
    uint32_t ahb = sb + A_HI_OFF(stage);
    uint32_t alb = sb + A_LO_OFF(stage);
    #pragma unroll
    for (int p = 0; p < 16; p++) {
        float v0 = xs[2 * p], v1 = xs[2 * p + 1];
        float e0, e1;
        if (!is_silu) {
            float t0 = (v0 - gv) * 1.75f;
            float t1 = (v1 - gv) * 1.75f;
            e0 = __expf(-t0 * t0);
            e1 = __expf(-t1 * t1);
        } else {
            e0 = v0 / (1.0f + __expf(-v0));
            e1 = v1 / (1.0f + __expf(-v1));
        }
        uint16_t h0, l0, h1, l1;
        split_bf16(e0, h0, l0);
        split_bf16(e1, h1, l1);
        uint32_t hp = ((uint32_t)h1 << 16) | h0;
        uint32_t lp = ((uint32_t)l1 << 16) | l0;
        int colb = ah * 64 + p * 4;
        uint32_t d = swaddr(0, am, colb);
        sts32(ahb + d, hp);
        sts32(alb + d, lp);
    }
}

// ---------------- main kernel ----------------
__global__ void __launch_bounds__(NTHREADS, 2)
kan_mma_kernel(const float* __restrict__ x,
               const float* __restrict__ grid,
               const float* __restrict__ bb,
               float* __restrict__ out) {
    extern __shared__ char smem[];
    uint32_t sb = smem_u32(smem);
    const int tid = threadIdx.x;
    const int wid = tid >> 5;
    const int lid = tid & 31;
    const int wm  = wid & 3;    // m quarter (32 rows)
    const int wn  = wid >> 2;   // n half (32 cols)

    const int row0 = blockIdx.y * BM;
    const int n0   = blockIdx.x * BN;

    const int am = tid >> 1;    // A fill row 0..127
    const int ah = tid & 1;     // A fill k-half

    float acc[2][4][4];
    #pragma unroll
    for (int mt = 0; mt < 2; mt++)
        #pragma unroll
        for (int nt = 0; nt < 4; nt++)
            #pragma unroll
            for (int q = 0; q < 4; q++) acc[mt][nt][q] = 0.0f;

    float xs[32];

    // prologue: chunk 0 (ib=0, gg=0) into stage 0
    load_x(x, row0, 0, am, ah, xs);
    fill_B_async(sb, 0, 0, n0, tid);
    CP_COMMIT();
    fill_A(sb, 0, 0, grid, am, ah, xs);
    CP_WAIT0();
    __syncthreads();

    int gg = 0, ib = 0;
    for (int c = 0; c < NCHUNK; c++) {
        const int s = c & 1;
        int ngg = gg + 1, nib = ib;
        if (ngg == 9) { ngg = 0; nib = ib + 1; }
        const bool has_next = (c + 1 < NCHUNK);

        if (has_next) {
            int kk = (ngg < 8) ? (ngg * IN_DIM + nib * KC) : (4096 + nib * KC);
            fill_B_async(sb, s ^ 1, kk, n0, tid);
            CP_COMMIT();
        }

        // ---- MMA over stage s (warp tile 32x32) ----
        const uint32_t Ah = sb + A_HI_OFF(s), Al = sb + A_LO_OFF(s);
        const uint32_t Bh = sb + B_HI_OFF(s), Bl = sb + B_LO_OFF(s);
        #pragma unroll
        for (int ks = 0; ks < 4; ks++) {
            const int acolb = ks * 32 + ((lid >> 4) << 4);
            uint32_t ahf[2][4], alf[2][4];
            #pragma unroll
            for (int mt = 0; mt < 2; mt++) {
                int row = wm * 32 + mt * 16 + (lid & 15);
                ldsm4(ahf[mt], swaddr(Ah, row, acolb));
                ldsm4(alf[mt], swaddr(Al, row, acolb));
            }
            const int bno = (lid & 7) + ((lid >> 4) << 3);
            const int bcolb = ks * 32 + (((lid >> 3) & 1) << 4);
            uint32_t bhf[2][4], blf[2][4];
            #pragma unroll
            for (int p = 0; p < 2; p++) {
                int row = wn * 32 + p * 16 + bno;
                ldsm4(bhf[p], swaddr(Bh, row, bcolb));
                ldsm4(blf[p], swaddr(Bl, row, bcolb));
            }
            #pragma unroll
            for (int mt = 0; mt < 2; mt++) {
                #pragma unroll
                for (int nt = 0; nt < 4; nt++) {
                    uint32_t b0h = bhf[nt >> 1][(nt & 1) * 2];
                    uint32_t b1h = bhf[nt >> 1][(nt & 1) * 2 + 1];
                    uint32_t b0l = blf[nt >> 1][(nt & 1) * 2];
                    uint32_t b1l = blf[nt >> 1][(nt & 1) * 2 + 1];
                    mma16816(acc[mt][nt], ahf[mt], b0h, b1h);   // hi*hi
                    mma16816(acc[mt][nt], ahf[mt], b0l, b1l);   // hi*lo
                    mma16816(acc[mt][nt], alf[mt], b0h, b1h);   // lo*hi
                }
            }
        }

        if (has_next) {
            if (ngg == 0) load_x(x, row0, nib, am, ah, xs);
            fill_A(sb, s ^ 1, ngg, grid, am, ah, xs);
        }
        CP_WAIT0();
        __syncthreads();
        gg = ngg; ib = nib;
    }

    // ---- epilogue: bias + store ----
    #pragma unroll
    for (int mt = 0; mt < 2; mt++) {
        int row = row0 + wm * 32 + mt * 16 + (lid >> 2);
        #pragma unroll
        for (int nt = 0; nt < 4; nt++) {
            int col = n0 + wn * 32 + nt * 8 + (lid & 3) * 2;
            float2 bv = *reinterpret_cast<const float2*>(bb + col);
            float2 o0, o1;
            o0.x = acc[mt][nt][0] + bv.x;
            o0.y = acc[mt][nt][1] + bv.y;
            o1.x = acc[mt][nt][2] + bv.x;
            o1.y = acc[mt][nt][3] + bv.y;
            *reinterpret_cast<float2*>(out + (size_t)row * OUT_DIM + col) = o0;
            *reinterpret_cast<float2*>(out + (size_t)(row + 8) * OUT_DIM + col) = o1;
        }
    }
}

// ---------------- launch ----------------
extern "C" void kernel_launch(void* const* d_in, const int* in_sizes, int n_in,
                              void* d_out, int out_size) {
    const float* x    = (const float*)d_in[0];
    const float* grid = (const float*)d_in[1];
    const float* sw   = (const float*)d_in[2];
    const float* bw   = (const float*)d_in[3];
    const float* bb   = (const float*)d_in[4];
    float* out = (float*)d_out;

    convert_b_kernel<<<dim3(16, 16, 9), dim3(32, 8)>>>(sw, bw);

    cudaFuncSetAttribute(kan_mma_kernel, cudaFuncAttributeMaxDynamicSharedMemorySize,
                         SMEM_TOTAL);
    dim3 g(OUT_DIM / BN, N_ROWS / BM);   // (8, 128) = 1024 CTAs
    kan_mma_kernel<<<g, NTHREADS, SMEM_TOTAL>>>(x, grid, bb, out);
}

// round 11
// speedup vs baseline: 2.0884x; 1.1100x over previous
#include <cuda_runtime.h>
#include <cuda_bf16.h>
#include <cstdint>

// ===========================================================================
// KANLayer via mma.sync (HMMA) bf16 split-precision GEMM, warp-specialized.
// out[n,o] = sum_k Avirt[n,k]*Bt[o,k] + bias[o],  K = 4608 virtual:
//   k = g*512 + i (g<8): Avirt = exp(-((x[n,i]-grid[g])*1.75)^2), Bt = spline_weight[i*8+g, o]
//   k = 4096 + i:        Avirt = silu(x[n,i]),                    Bt = base_w[o, i]
// 3-pass split: D = Ahi*Bhi + Ahi*Blo + Alo*Bhi  (fp32 accumulators)
// R11: warps 0-3 producers (expand A, cp.async B), warps 4-7 consumers (MMA),
//      named-barrier full/empty handshake over 2-stage smem buffer.
// ===========================================================================

#define N_ROWS  16384
#define IN_DIM  512
#define OUT_DIM 512
#define KTOT    4608
#define KC      64
#define NCHUNK  72
#define BM      128
#define BN      64
#define NTHREADS 256

// per-stage smem: Ahi 16K, Alo 16K, Bhi 8K, Blo 8K = 48KB; 2 stages = 96KB
#define STAGE_BYTES  49152
#define A_HI_OFF(s)  ((s) * STAGE_BYTES + 0)
#define A_LO_OFF(s)  ((s) * STAGE_BYTES + 16384)
#define B_HI_OFF(s)  ((s) * STAGE_BYTES + 32768)
#define B_LO_OFF(s)  ((s) * STAGE_BYTES + 40960)
#define SMEM_TOTAL   (2 * STAGE_BYTES)

// named barriers: FULL(s) = 1+s, EMPTY(s) = 3+s
#define BAR_FULL(s)  (1 + (s))
#define BAR_EMPTY(s) (3 + (s))

// Pre-converted B: Bt_hi/lo[o][k]  (bf16, k contiguous)
__device__ __nv_bfloat16 g_Bt_hi[OUT_DIM * KTOT];
__device__ __nv_bfloat16 g_Bt_lo[OUT_DIM * KTOT];

// ---------------- helpers ----------------
__device__ __forceinline__ uint32_t smem_u32(const void* p) {
    uint32_t a;
    asm("{ .reg .u64 t; cvta.to.shared.u64 t, %1; cvt.u32.u64 %0, t; }" : "=r"(a) : "l"(p));
    return a;
}
__device__ __forceinline__ uint32_t swaddr(uint32_t base, int row, int colb) {
    return base + row * 128 + (colb ^ ((row & 7) << 4));
}
__device__ __forceinline__ void ldsm4(uint32_t r[4], uint32_t addr) {
    asm volatile("ldmatrix.sync.aligned.m8n8.x4.shared.b16 {%0,%1,%2,%3}, [%4];"
                 : "=r"(r[0]), "=r"(r[1]), "=r"(r[2]), "=r"(r[3]) : "r"(addr));
}
__device__ __forceinline__ void mma16816(float c[4], const uint32_t a[4],
                                         uint32_t b0, uint32_t b1) {
    asm volatile(
        "mma.sync.aligned.m16n8k16.row.col.f32.bf16.bf16.f32 "
        "{%0,%1,%2,%3}, {%4,%5,%6,%7}, {%8,%9}, {%0,%1,%2,%3};"
        : "+f"(c[0]), "+f"(c[1]), "+f"(c[2]), "+f"(c[3])
        : "r"(a[0]), "r"(a[1]), "r"(a[2]), "r"(a[3]), "r"(b0), "r"(b1));
}
__device__ __forceinline__ void split_bf16(float v, uint16_t& hi, uint16_t& lo) {
    __nv_bfloat16 h = __float2bfloat16(v);
    float r = v - __bfloat162float(h);
    __nv_bfloat16 l = __float2bfloat16(r);
    hi = __bfloat16_as_ushort(h);
    lo = __bfloat16_as_ushort(l);
}
__device__ __forceinline__ void sts128(uint32_t addr, uint4 v) {
    asm volatile("st.shared.v4.b32 [%0], {%1,%2,%3,%4};"
                 :: "r"(addr), "r"(v.x), "r"(v.y), "r"(v.z), "r"(v.w) : "memory");
}
__device__ __forceinline__ void cp16(uint32_t dst, const void* src) {
    asm volatile("cp.async.cg.shared.global [%0], [%1], 16;"
                 :: "r"(dst), "l"(src) : "memory");
}
#define CP_COMMIT() asm volatile("cp.async.commit_group;" ::: "memory")
#define CP_WAIT0()  asm volatile("cp.async.wait_group 0;" ::: "memory")
__device__ __forceinline__ void bar_sync(int id) {
    asm volatile("bar.sync %0, %1;" :: "r"(id), "n"(NTHREADS) : "memory");
}
__device__ __forceinline__ void bar_arrive(int id) {
    asm volatile("bar.arrive %0, %1;" :: "r"(id), "n"(NTHREADS) : "memory");
}

// ---------------- pre-pass: build Bt_hi/lo ----------------
__global__ void convert_b_kernel(const float* __restrict__ sw,
                                 const float* __restrict__ bw) {
    __shared__ float tile[32][33];
    int g  = blockIdx.z;
    int i0 = blockIdx.x * 32, o0 = blockIdx.y * 32;
    int tx = threadIdx.x, ty = threadIdx.y;   // (32, 8)
    if (g < 8) {
        #pragma unroll
        for (int j = 0; j < 32; j += 8)
            tile[ty + j][tx] = sw[((size_t)(i0 + ty + j) * 8 + g) * OUT_DIM + o0 + tx];
        __syncthreads();
        #pragma unroll
        for (int j = 0; j < 32; j += 8) {
            float v = tile[tx][ty + j];
            int o = o0 + ty + j, i = i0 + tx;
            uint16_t h, l; split_bf16(v, h, l);
            size_t idx = (size_t)o * KTOT + g * IN_DIM + i;
            g_Bt_hi[idx] = __ushort_as_bfloat16(h);
            g_Bt_lo[idx] = __ushort_as_bfloat16(l);
        }
    } else {
        #pragma unroll
        for (int j = 0; j < 32; j += 8) {
            int o = o0 + ty + j, i = i0 + tx;
            float v = bw[(size_t)o * IN_DIM + i];
            uint16_t h, l; split_bf16(v, h, l);
            size_t idx = (size_t)o * KTOT + 4096 + i;
            g_Bt_hi[idx] = __ushort_as_bfloat16(h);
            g_Bt_lo[idx] = __ushort_as_bfloat16(l);
        }
    }
}

// ---------------- main kernel ----------------
__global__ void __launch_bounds__(NTHREADS, 2)
kan_mma_kernel(const float* __restrict__ x,
               const float* __restrict__ grid,
               const float* __restrict__ bb,
               float* __restrict__ out) {
    extern __shared__ char smem[];
    uint32_t sb = smem_u32(smem);
    const int tid = threadIdx.x;
    const int wid = tid >> 5;
    const int lid = tid & 31;

    const int row0 = blockIdx.y * BM;
    const int n0   = blockIdx.x * BN;

    if (wid < 4) {
        // ================= PRODUCER (threads 0..127) =================
        const int pt = tid;            // row within A tile: 0..127
        float xs[64];

        int gg = 0, ib = 0;
        for (int c = 0; c < NCHUNK; c++) {
            const int s = c & 1;
            if (c >= 2) bar_sync(BAR_EMPTY(s));

            if (gg == 0) {
                const float4* xp = reinterpret_cast<const float4*>(
                    x + (size_t)(row0 + pt) * IN_DIM + ib * KC);
                #pragma unroll
                for (int j = 0; j < 16; j++) {
                    float4 v = xp[j];
                    xs[4 * j] = v.x; xs[4 * j + 1] = v.y;
                    xs[4 * j + 2] = v.z; xs[4 * j + 3] = v.w;
                }
            }

            // ---- B tile via cp.async ----
            {
                const int kk = (gg < 8) ? (gg * IN_DIM + ib * KC) : (4096 + ib * KC);
                const int brow = pt >> 1;
                const int ub = (pt & 1) * 4;
                size_t goff = (size_t)(n0 + brow) * KTOT + kk + ub * 8;
                uint32_t bh = sb + B_HI_OFF(s);
                uint32_t bl = sb + B_LO_OFF(s);
                #pragma unroll
                for (int u = 0; u < 4; u++) {
                    uint32_t d = swaddr(0, brow, (ub + u) * 16);
                    cp16(bh + d, g_Bt_hi + goff + u * 8);
                    cp16(bl + d, g_Bt_lo + goff + u * 8);
                }
                CP_COMMIT();
            }

            // ---- A expansion: 64 values, packed STS.128 ----
            {
                const bool is_silu = (gg == 8);
                const float gv = is_silu ? 0.0f : __ldg(grid + gg);
                uint32_t ahb = sb + A_HI_OFF(s);
                uint32_t alb = sb + A_LO_OFF(s);
                #pragma unroll
                for (int c16 = 0; c16 < 8; c16++) {
                    uint32_t hw[4], lw[4];
                    #pragma unroll
                    for (int q = 0; q < 4; q++) {
                        float v0 = xs[c16 * 8 + 2 * q];
                        float v1 = xs[c16 * 8 + 2 * q + 1];
                        float e0, e1;
                        if (!is_silu) {
                            float t0 = (v0 - gv) * 1.75f;
                            float t1 = (v1 - gv) * 1.75f;
                            e0 = __expf(-t0 * t0);
                            e1 = __expf(-t1 * t1);
                        } else {
                            e0 = v0 / (1.0f + __expf(-v0));
                            e1 = v1 / (1.0f + __expf(-v1));
                        }
                        uint16_t h0, l0, h1, l1;
                        split_bf16(e0, h0, l0);
                        split_bf16(e1, h1, l1);
                        hw[q] = ((uint32_t)h1 << 16) | h0;
                        lw[q] = ((uint32_t)l1 << 16) | l0;
                    }
                    uint32_t d = swaddr(0, pt, c16 * 16);
                    sts128(ahb + d, make_uint4(hw[0], hw[1], hw[2], hw[3]));
                    sts128(alb + d, make_uint4(lw[0], lw[1], lw[2], lw[3]));
                }
            }

            CP_WAIT0();
            bar_arrive(BAR_FULL(s));

            if (++gg == 9) { gg = 0; ib++; }
        }
    } else {
        // ================= CONSUMER (threads 128..255) =================
        const int wm = wid - 4;        // 0..3 -> rows wm*32..+31, full N=64

        float acc[2][8][4];
        #pragma unroll
        for (int mt = 0; mt < 2; mt++)
            #pragma unroll
            for (int nt = 0; nt < 8; nt++)
                #pragma unroll
                for (int q = 0; q < 4; q++) acc[mt][nt][q] = 0.0f;

        const int bno   = (lid & 7) + ((lid >> 4) << 3);
        const int bcsel = ((lid >> 3) & 1) << 4;
        const int arow  = lid & 15;
        const int acsel = (lid >> 4) << 4;

        for (int c = 0; c < NCHUNK; c++) {
            const int s = c & 1;
            bar_sync(BAR_FULL(s));

            const uint32_t Ah = sb + A_HI_OFF(s), Al = sb + A_LO_OFF(s);
            const uint32_t Bh = sb + B_HI_OFF(s), Bl = sb + B_LO_OFF(s);
            #pragma unroll
            for (int ks = 0; ks < 4; ks++) {
                const int acolb = ks * 32 + acsel;
                uint32_t ahf[2][4], alf[2][4];
                #pragma unroll
                for (int mt = 0; mt < 2; mt++) {
                    int row = wm * 32 + mt * 16 + arow;
                    ldsm4(ahf[mt], swaddr(Ah, row, acolb));
                    ldsm4(alf[mt], swaddr(Al, row, acolb));
                }
                const int bcolb = ks * 32 + bcsel;
                #pragma unroll
                for (int p = 0; p < 4; p++) {
                    uint32_t bh4[4], bl4[4];
                    int brow = p * 16 + bno;
                    ldsm4(bh4, swaddr(Bh, brow, bcolb));
                    ldsm4(bl4, swaddr(Bl, brow, bcolb));
                    #pragma unroll
                    for (int mt = 0; mt < 2; mt++) {
                        #pragma unroll
                        for (int j = 0; j < 2; j++) {
                            const int nt = p * 2 + j;
                            mma16816(acc[mt][nt], ahf[mt], bh4[j * 2], bh4[j * 2 + 1]);
                            mma16816(acc[mt][nt], ahf[mt], bl4[j * 2], bl4[j * 2 + 1]);
                            mma16816(acc[mt][nt], alf[mt], bh4[j * 2], bh4[j * 2 + 1]);
                        }
                    }
                }
            }

            bar_arrive(BAR_EMPTY(s));
        }

        // ---- epilogue: bias + store ----
        #pragma unroll
        for (int mt = 0; mt < 2; mt++) {
            int row = row0 + wm * 32 + mt * 16 + (lid >> 2);
            #pragma unroll
            for (int nt = 0; nt < 8; nt++) {
                int col = n0 + nt * 8 + (lid & 3) * 2;
                float2 bv = *reinterpret_cast<const float2*>(bb + col);
                float2 o0, o1;
                o0.x = acc[mt][nt][0] + bv.x;
                o0.y = acc[mt][nt][1] + bv.y;
                o1.x = acc[mt][nt][2] + bv.x;
                o1.y = acc[mt][nt][3] + bv.y;
                *reinterpret_cast<float2*>(out + (size_t)row * OUT_DIM + col) = o0;
                *reinterpret_cast<float2*>(out + (size_t)(row + 8) * OUT_DIM + col) = o1;
            }
        }
    }
}

// ---------------- launch ----------------
extern "C" void kernel_launch(void* const* d_in, const int* in_sizes, int n_in,
                              void* d_out, int out_size) {
    const float* x    = (const float*)d_in[0];
    const float* grid = (const float*)d_in[1];
    const float* sw   = (const float*)d_in[2];
    const float* bw   = (const float*)d_in[3];
    const float* bb   = (const float*)d_in[4];
    float* out = (float*)d_out;

    convert_b_kernel<<<dim3(16, 16, 9), dim3(32, 8)>>>(sw, bw);

    cudaFuncSetAttribute(kan_mma_kernel, cudaFuncAttributeMaxDynamicSharedMemorySize,
                         SMEM_TOTAL);
    dim3 g(OUT_DIM / BN, N_ROWS / BM);   // (8, 128) = 1024 CTAs
    kan_mma_kernel<<<g, NTHREADS, SMEM_TOTAL>>>(x, grid, bb, out);
}

// round 13
// speedup vs baseline: 2.3615x; 1.1308x over previous
#include <cuda_runtime.h>
#include <cuda_bf16.h>
#include <cstdint>

// ===========================================================================
// KANLayer via mma.sync (HMMA) bf16 split-precision GEMM, warp-specialized.
// out[n,o] = sum_k Avirt[n,k]*Bt[o,k] + bias[o],  K = 4608 virtual:
//   k = g*512 + i (g<8): Avirt = exp(-((x[n,i]-grid[g])*1.75)^2), Bt = spline_weight[i*8+g, o]
//   k = 4096 + i:        Avirt = silu(x[n,i]),                    Bt = base_w[o, i]
// 3-pass split: D = Ahi*Bhi + Ahi*Blo + Alo*Bhi  (fp32 accumulators)
// R12: 512-thread CTA (8 producer + 8 consumer warps), BM=128 BN=128,
//      3-stage smem pipeline, truncation-split (PRMT/bf16x2-cvt) expansion.
// ===========================================================================

#define N_ROWS  16384
#define IN_DIM  512
#define OUT_DIM 512
#define KTOT    4608
#define KC      64
#define NCHUNK  72
#define BM      128
#define BN      128
#define NTHREADS 512
#define NSTAGE  3

// per-stage smem: Ahi 16K, Alo 16K, Bhi 16K, Blo 16K = 64KB; 3 stages = 192KB
#define STAGE_BYTES  65536
#define A_HI_OFF(s)  ((s) * STAGE_BYTES + 0)
#define A_LO_OFF(s)  ((s) * STAGE_BYTES + 16384)
#define B_HI_OFF(s)  ((s) * STAGE_BYTES + 32768)
#define B_LO_OFF(s)  ((s) * STAGE_BYTES + 49152)
#define SMEM_TOTAL   (NSTAGE * STAGE_BYTES)

// named barriers: FULL(s) = 1+s, EMPTY(s) = 4+s
#define BAR_FULL(s)  (1 + (s))
#define BAR_EMPTY(s) (4 + (s))

// Pre-converted B: Bt_hi/lo[o][k]  (bf16, k contiguous)
__device__ __nv_bfloat16 g_Bt_hi[OUT_DIM * KTOT];
__device__ __nv_bfloat16 g_Bt_lo[OUT_DIM * KTOT];

// ---------------- helpers ----------------
__device__ __forceinline__ uint32_t smem_u32(const void* p) {
    uint32_t a;
    asm("{ .reg .u64 t; cvta.to.shared.u64 t, %1; cvt.u32.u64 %0, t; }" : "=r"(a) : "l"(p));
    return a;
}
__device__ __forceinline__ uint32_t swaddr(uint32_t base, int row, int colb) {
    return base + row * 128 + (colb ^ ((row & 7) << 4));
}
__device__ __forceinline__ void ldsm4(uint32_t r[4], uint32_t addr) {
    asm volatile("ldmatrix.sync.aligned.m8n8.x4.shared.b16 {%0,%1,%2,%3}, [%4];"
                 : "=r"(r[0]), "=r"(r[1]), "=r"(r[2]), "=r"(r[3]) : "r"(addr));
}
__device__ __forceinline__ void mma16816(float c[4], const uint32_t a[4],
                                         uint32_t b0, uint32_t b1) {
    asm volatile(
        "mma.sync.aligned.m16n8k16.row.col.f32.bf16.bf16.f32 "
        "{%0,%1,%2,%3}, {%4,%5,%6,%7}, {%8,%9}, {%0,%1,%2,%3};"
        : "+f"(c[0]), "+f"(c[1]), "+f"(c[2]), "+f"(c[3])
        : "r"(a[0]), "r"(a[1]), "r"(a[2]), "r"(a[3]), "r"(b0), "r"(b1));
}
// rn split (pre-pass only, precision of B matters most)
__device__ __forceinline__ void split_bf16(float v, uint16_t& hi, uint16_t& lo) {
    __nv_bfloat16 h = __float2bfloat16(v);
    float r = v - __bfloat162float(h);
    __nv_bfloat16 l = __float2bfloat16(r);
    hi = __bfloat16_as_ushort(h);
    lo = __bfloat16_as_ushort(l);
}
// pack two residuals into bf16x2 with one cvt (first source -> upper half)
__device__ __forceinline__ uint32_t cvt_bf16x2(float hi_val, float lo_val) {
    uint32_t r;
    asm("cvt.rn.bf16x2.f32 %0, %1, %2;" : "=r"(r) : "f"(hi_val), "f"(lo_val));
    return r;
}
__device__ __forceinline__ void sts128(uint32_t addr, uint4 v) {
    asm volatile("st.shared.v4.b32 [%0], {%1,%2,%3,%4};"
                 :: "r"(addr), "r"(v.x), "r"(v.y), "r"(v.z), "r"(v.w) : "memory");
}
__device__ __forceinline__ void cp16(uint32_t dst, const void* src) {
    asm volatile("cp.async.cg.shared.global [%0], [%1], 16;"
                 :: "r"(dst), "l"(src) : "memory");
}
#define CP_COMMIT() asm volatile("cp.async.commit_group;" ::: "memory")
#define CP_WAIT0()  asm volatile("cp.async.wait_group 0;" ::: "memory")
__device__ __forceinline__ void bar_sync(int id) {
    asm volatile("bar.sync %0, %1;" :: "r"(id), "n"(NTHREADS) : "memory");
}
__device__ __forceinline__ void bar_arrive(int id) {
    asm volatile("bar.arrive %0, %1;" :: "r"(id), "n"(NTHREADS) : "memory");
}

// ---------------- pre-pass: build Bt_hi/lo ----------------
__global__ void convert_b_kernel(const float* __restrict__ sw,
                                 const float* __restrict__ bw) {
    __shared__ float tile[32][33];
    int g  = blockIdx.z;
    int i0 = blockIdx.x * 32, o0 = blockIdx.y * 32;
    int tx = threadIdx.x, ty = threadIdx.y;   // (32, 8)
    if (g < 8) {
        #pragma unroll
        for (int j = 0; j < 32; j += 8)
            tile[ty + j][tx] = sw[((size_t)(i0 + ty + j) * 8 + g) * OUT_DIM + o0 + tx];
        __syncthreads();
        #pragma unroll
        for (int j = 0; j < 32; j += 8) {
            float v = tile[tx][ty + j];
            int o = o0 + ty + j, i = i0 + tx;
            uint16_t h, l; split_bf16(v, h, l);
            size_t idx = (size_t)o * KTOT + g * IN_DIM + i;
            g_Bt_hi[idx] = __ushort_as_bfloat16(h);
            g_Bt_lo[idx] = __ushort_as_bfloat16(l);
        }
    } else {
        #pragma unroll
        for (int j = 0; j < 32; j += 8) {
            int o = o0 + ty + j, i = i0 + tx;
            float v = bw[(size_t)o * IN_DIM + i];
            uint16_t h, l; split_bf16(v, h, l);
            size_t idx = (size_t)o * KTOT + 4096 + i;
            g_Bt_hi[idx] = __ushort_as_bfloat16(h);
            g_Bt_lo[idx] = __ushort_as_bfloat16(l);
        }
    }
}

// ---------------- main kernel ----------------
__global__ void __launch_bounds__(NTHREADS, 1)
kan_mma_kernel(const float* __restrict__ x,
               const float* __restrict__ grid,
               const float* __restrict__ bb,
               float* __restrict__ out) {
    extern __shared__ char smem[];
    uint32_t sb = smem_u32(smem);
    const int tid = threadIdx.x;
    const int wid = tid >> 5;
    const int lid = tid & 31;

    const int row0 = blockIdx.y * BM;
    const int n0   = blockIdx.x * BN;

    if (wid < 8) {
        // ================= PRODUCER (threads 0..255) =================
        const int arow = tid >> 1;      // A row 0..127
        const int half = tid & 1;       // k cols [half*32, half*32+32)
        float xs[32];

        int gg = 0, ib = 0, s = 0;
        for (int c = 0; c < NCHUNK; c++) {
            if (c >= NSTAGE) bar_sync(BAR_EMPTY(s));

            if (gg == 0) {
                const float4* xp = reinterpret_cast<const float4*>(
                    x + (size_t)(row0 + arow) * IN_DIM + ib * KC + half * 32);
                #pragma unroll
                for (int j = 0; j < 8; j++) {
                    float4 v = xp[j];
                    xs[4 * j] = v.x; xs[4 * j + 1] = v.y;
                    xs[4 * j + 2] = v.z; xs[4 * j + 3] = v.w;
                }
            }

            // ---- B tile (128 rows x 64 k, hi+lo) via cp.async ----
            {
                const int kk = (gg < 8) ? (gg * IN_DIM + ib * KC) : (4096 + ib * KC);
                const int brow = tid >> 1;
                const int ub = (tid & 1) * 4;
                size_t goff = (size_t)(n0 + brow) * KTOT + kk + ub * 8;
                uint32_t bh = sb + B_HI_OFF(s);
                uint32_t bl = sb + B_LO_OFF(s);
                #pragma unroll
                for (int u = 0; u < 4; u++) {
                    uint32_t d = swaddr(0, brow, (ub + u) * 16);
                    cp16(bh + d, g_Bt_hi + goff + u * 8);
                    cp16(bl + d, g_Bt_lo + goff + u * 8);
                }
                CP_COMMIT();
            }

            // ---- A expansion: 32 values, truncation split, packed STS.128 ----
            {
                const bool is_silu = (gg == 8);
                const float gv = is_silu ? 0.0f : __ldg(grid + gg);
                uint32_t ahb = sb + A_HI_OFF(s);
                uint32_t alb = sb + A_LO_OFF(s);
                #pragma unroll
                for (int c16 = 0; c16 < 4; c16++) {
                    uint32_t hw[4], lw[4];
                    #pragma unroll
                    for (int q = 0; q < 4; q++) {
                        float v0 = xs[c16 * 8 + 2 * q];
                        float v1 = xs[c16 * 8 + 2 * q + 1];
                        float e0, e1;
                        if (!is_silu) {
                            float t0 = (v0 - gv) * 1.75f;
                            float t1 = (v1 - gv) * 1.75f;
                            e0 = __expf(-t0 * t0);
                            e1 = __expf(-t1 * t1);
                        } else {
                            e0 = v0 / (1.0f + __expf(-v0));
                            e1 = v1 / (1.0f + __expf(-v1));
                        }
                        uint32_t b0 = __float_as_uint(e0);
                        uint32_t b1 = __float_as_uint(e1);
                        hw[q] = __byte_perm(b0, b1, 0x7632);      // [hi1:hi0]
                        float l0 = e0 - __uint_as_float(b0 & 0xFFFF0000u);
                        float l1 = e1 - __uint_as_float(b1 & 0xFFFF0000u);
                        lw[q] = cvt_bf16x2(l1, l0);               // [lo1:lo0]
                    }
                    uint32_t d = swaddr(0, arow, half * 64 + c16 * 16);
                    sts128(ahb + d, make_uint4(hw[0], hw[1], hw[2], hw[3]));
                    sts128(alb + d, make_uint4(lw[0], lw[1], lw[2], lw[3]));
                }
            }

            CP_WAIT0();
            bar_arrive(BAR_FULL(s));

            if (++gg == 9) { gg = 0; ib++; }
            if (++s == NSTAGE) s = 0;
        }
    } else {
        // ================= CONSUMER (threads 256..511) =================
        const int wc = wid - 8;        // 0..7
        const int wm = wc & 3;         // row block (32 rows)
        const int wn = wc >> 2;        // col half (64 cols)

        float acc[2][8][4];
        #pragma unroll
        for (int mt = 0; mt < 2; mt++)
            #pragma unroll
            for (int nt = 0; nt < 8; nt++)
                #pragma unroll
                for (int q = 0; q < 4; q++) acc[mt][nt][q] = 0.0f;

        const int bno   = (lid & 7) + ((lid >> 4) << 3);
        const int bcsel = ((lid >> 3) & 1) << 4;
        const int arow  = lid & 15;
        const int acsel = (lid >> 4) << 4;

        int s = 0;
        for (int c = 0; c < NCHUNK; c++) {
            bar_sync(BAR_FULL(s));

            const uint32_t Ah = sb + A_HI_OFF(s), Al = sb + A_LO_OFF(s);
            const uint32_t Bh = sb + B_HI_OFF(s), Bl = sb + B_LO_OFF(s);
            #pragma unroll
            for (int ks = 0; ks < 4; ks++) {
                const int acolb = ks * 32 + acsel;
                uint32_t ahf[2][4], alf[2][4];
                #pragma unroll
                for (int mt = 0; mt < 2; mt++) {
                    int row = wm * 32 + mt * 16 + arow;
                    ldsm4(ahf[mt], swaddr(Ah, row, acolb));
                    ldsm4(alf[mt], swaddr(Al, row, acolb));
                }
                const int bcolb = ks * 32 + bcsel;
                #pragma unroll
                for (int p = 0; p < 4; p++) {
                    uint32_t bh4[4], bl4[4];
                    int brow = wn * 64 + p * 16 + bno;
                    ldsm4(bh4, swaddr(Bh, brow, bcolb));
                    ldsm4(bl4, swaddr(Bl, brow, bcolb));
                    #pragma unroll
                    for (int mt = 0; mt < 2; mt++) {
                        #pragma unroll
                        for (int j = 0; j < 2; j++) {
                            const int nt = p * 2 + j;
                            mma16816(acc[mt][nt], ahf[mt], bh4[j * 2], bh4[j * 2 + 1]);
                            mma16816(acc[mt][nt], ahf[mt], bl4[j * 2], bl4[j * 2 + 1]);
                            mma16816(acc[mt][nt], alf[mt], bh4[j * 2], bh4[j * 2 + 1]);
                        }
                    }
                }
            }

            bar_arrive(BAR_EMPTY(s));
            if (++s == NSTAGE) s = 0;
        }

        // ---- epilogue: bias + store ----
        #pragma unroll
        for (int mt = 0; mt < 2; mt++) {
            int row = row0 + wm * 32 + mt * 16 + (lid >> 2);
            #pragma unroll
            for (int nt = 0; nt < 8; nt++) {
                int col = n0 + wn * 64 + nt * 8 + (lid & 3) * 2;
                float2 bv = *reinterpret_cast<const float2*>(bb + col);
                float2 o0, o1;
                o0.x = acc[mt][nt][0] + bv.x;
                o0.y = acc[mt][nt][1] + bv.y;
                o1.x = acc[mt][nt][2] + bv.x;
                o1.y = acc[mt][nt][3] + bv.y;
                *reinterpret_cast<float2*>(out + (size_t)row * OUT_DIM + col) = o0;
                *reinterpret_cast<float2*>(out + (size_t)(row + 8) * OUT_DIM + col) = o1;
            }
        }
    }
}

// ---------------- launch ----------------
extern "C" void kernel_launch(void* const* d_in, const int* in_sizes, int n_in,
                              void* d_out, int out_size) {
    const float* x    = (const float*)d_in[0];
    const float* grid = (const float*)d_in[1];
    const float* sw   = (const float*)d_in[2];
    const float* bw   = (const float*)d_in[3];
    const float* bb   = (const float*)d_in[4];
    float* out = (float*)d_out;

    convert_b_kernel<<<dim3(16, 16, 9), dim3(32, 8)>>>(sw, bw);

    cudaFuncSetAttribute(kan_mma_kernel, cudaFuncAttributeMaxDynamicSharedMemorySize,
                         SMEM_TOTAL);
    dim3 g(OUT_DIM / BN, N_ROWS / BM);   // (4, 128) = 512 CTAs
    kan_mma_kernel<<<g, NTHREADS, SMEM_TOTAL>>>(x, grid, bb, out);
}

// round 14
// speedup vs baseline: 2.4315x; 1.0297x over previous
#include <cuda_runtime.h>
#include <cuda_bf16.h>
#include <cstdint>

// ===========================================================================
// KANLayer via mma.sync (HMMA) bf16 split-precision GEMM, warp-specialized.
// out[n,o] = sum_k Avirt[n,k]*Bt[o,k] + bias[o],  K = 4608 virtual:
//   k = g*512 + i (g<8): Avirt = exp(-((x[n,i]-grid[g])*1.75)^2), Bt = spline_weight[i*8+g, o]
//   k = 4096 + i:        Avirt = silu(x[n,i]),                    Bt = base_w[o, i]
// 3-pass split: D = Ahi*Bhi + Ahi*Blo + Alo*Bhi  (fp32 accumulators)
// R14: B cp.async prefetched one chunk ahead (wait_group 1); x prefetched
//      after silu chunk; ex2-based expansion. 512 thr, 8P+8C warps, 3 stages.
// ===========================================================================

#define N_ROWS  16384
#define IN_DIM  512
#define OUT_DIM 512
#define KTOT    4608
#define KC      64
#define NCHUNK  72
#define BM      128
#define BN      128
#define NTHREADS 512
#define NSTAGE  3

#define STAGE_BYTES  65536
#define A_HI_OFF(s)  ((s) * STAGE_BYTES + 0)
#define A_LO_OFF(s)  ((s) * STAGE_BYTES + 16384)
#define B_HI_OFF(s)  ((s) * STAGE_BYTES + 32768)
#define B_LO_OFF(s)  ((s) * STAGE_BYTES + 49152)
#define SMEM_TOTAL   (NSTAGE * STAGE_BYTES)

#define BAR_FULL(s)  (1 + (s))
#define BAR_EMPTY(s) (4 + (s))

__device__ __nv_bfloat16 g_Bt_hi[OUT_DIM * KTOT];
__device__ __nv_bfloat16 g_Bt_lo[OUT_DIM * KTOT];

// ---------------- helpers ----------------
__device__ __forceinline__ uint32_t smem_u32(const void* p) {
    uint32_t a;
    asm("{ .reg .u64 t; cvta.to.shared.u64 t, %1; cvt.u32.u64 %0, t; }" : "=r"(a) : "l"(p));
    return a;
}
__device__ __forceinline__ uint32_t swaddr(uint32_t base, int row, int colb) {
    return base + row * 128 + (colb ^ ((row & 7) << 4));
}
__device__ __forceinline__ void ldsm4(uint32_t r[4], uint32_t addr) {
    asm volatile("ldmatrix.sync.aligned.m8n8.x4.shared.b16 {%0,%1,%2,%3}, [%4];"
                 : "=r"(r[0]), "=r"(r[1]), "=r"(r[2]), "=r"(r[3]) : "r"(addr));
}
__device__ __forceinline__ void mma16816(float c[4], const uint32_t a[4],
                                         uint32_t b0, uint32_t b1) {
    asm volatile(
        "mma.sync.aligned.m16n8k16.row.col.f32.bf16.bf16.f32 "
        "{%0,%1,%2,%3}, {%4,%5,%6,%7}, {%8,%9}, {%0,%1,%2,%3};"
        : "+f"(c[0]), "+f"(c[1]), "+f"(c[2]), "+f"(c[3])
        : "r"(a[0]), "r"(a[1]), "r"(a[2]), "r"(a[3]), "r"(b0), "r"(b1));
}
__device__ __forceinline__ void split_bf16(float v, uint16_t& hi, uint16_t& lo) {
    __nv_bfloat16 h = __float2bfloat16(v);
    float r = v - __bfloat162float(h);
    __nv_bfloat16 l = __float2bfloat16(r);
    hi = __bfloat16_as_ushort(h);
    lo = __bfloat16_as_ushort(l);
}
__device__ __forceinline__ uint32_t cvt_bf16x2(float hi_val, float lo_val) {
    uint32_t r;
    asm("cvt.rn.bf16x2.f32 %0, %1, %2;" : "=r"(r) : "f"(hi_val), "f"(lo_val));
    return r;
}
__device__ __forceinline__ float ex2f(float a) {
    float r;
    asm("ex2.approx.f32 %0, %1;" : "=f"(r) : "f"(a));
    return r;
}
__device__ __forceinline__ float rcpf(float a) {
    float r;
    asm("rcp.approx.f32 %0, %1;" : "=f"(r) : "f"(a));
    return r;
}
__device__ __forceinline__ void sts128(uint32_t addr, uint4 v) {
    asm volatile("st.shared.v4.b32 [%0], {%1,%2,%3,%4};"
                 :: "r"(addr), "r"(v.x), "r"(v.y), "r"(v.z), "r"(v.w) : "memory");
}
__device__ __forceinline__ void cp16(uint32_t dst, const void* src) {
    asm volatile("cp.async.cg.shared.global [%0], [%1], 16;"
                 :: "r"(dst), "l"(src) : "memory");
}
#define CP_COMMIT() asm volatile("cp.async.commit_group;" ::: "memory")
#define CP_WAIT0()  asm volatile("cp.async.wait_group 0;" ::: "memory")
#define CP_WAIT1()  asm volatile("cp.async.wait_group 1;" ::: "memory")
__device__ __forceinline__ void bar_sync(int id) {
    asm volatile("bar.sync %0, %1;" :: "r"(id), "n"(NTHREADS) : "memory");
}
__device__ __forceinline__ void bar_arrive(int id) {
    asm volatile("bar.arrive %0, %1;" :: "r"(id), "n"(NTHREADS) : "memory");
}

// ---------------- pre-pass: build Bt_hi/lo ----------------
__global__ void convert_b_kernel(const float* __restrict__ sw,
                                 const float* __restrict__ bw) {
    __shared__ float tile[32][33];
    int g  = blockIdx.z;
    int i0 = blockIdx.x * 32, o0 = blockIdx.y * 32;
    int tx = threadIdx.x, ty = threadIdx.y;
    if (g < 8) {
        #pragma unroll
        for (int j = 0; j < 32; j += 8)
            tile[ty + j][tx] = sw[((size_t)(i0 + ty + j) * 8 + g) * OUT_DIM + o0 + tx];
        __syncthreads();
        #pragma unroll
        for (int j = 0; j < 32; j += 8) {
            float v = tile[tx][ty + j];
            int o = o0 + ty + j, i = i0 + tx;
            uint16_t h, l; split_bf16(v, h, l);
            size_t idx = (size_t)o * KTOT + g * IN_DIM + i;
            g_Bt_hi[idx] = __ushort_as_bfloat16(h);
            g_Bt_lo[idx] = __ushort_as_bfloat16(l);
        }
    } else {
        #pragma unroll
        for (int j = 0; j < 32; j += 8) {
            int o = o0 + ty + j, i = i0 + tx;
            float v = bw[(size_t)o * IN_DIM + i];
            uint16_t h, l; split_bf16(v, h, l);
            size_t idx = (size_t)o * KTOT + 4096 + i;
            g_Bt_hi[idx] = __ushort_as_bfloat16(h);
            g_Bt_lo[idx] = __ushort_as_bfloat16(l);
        }
    }
}

// ---------------- main kernel ----------------
__global__ void __launch_bounds__(NTHREADS, 1)
kan_mma_kernel(const float* __restrict__ x,
               const float* __restrict__ grid,
               const float* __restrict__ bb,
               float* __restrict__ out) {
    extern __shared__ char smem[];
    uint32_t sb = smem_u32(smem);
    const int tid = threadIdx.x;
    const int wid = tid >> 5;
    const int lid = tid & 31;

    const int row0 = blockIdx.y * BM;
    const int n0   = blockIdx.x * BN;

    if (wid < 8) {
        // ================= PRODUCER (threads 0..255) =================
        const int arow = tid >> 1;
        const int half = tid & 1;
        const int brow = tid >> 1;
        const int ub   = (tid & 1) * 4;
        float xs[32];

        // x prologue (ib = 0)
        {
            const float4* xp = reinterpret_cast<const float4*>(
                x + (size_t)(row0 + arow) * IN_DIM + half * 32);
            #pragma unroll
            for (int j = 0; j < 8; j++) {
                float4 v = xp[j];
                xs[4 * j] = v.x; xs[4 * j + 1] = v.y;
                xs[4 * j + 2] = v.z; xs[4 * j + 3] = v.w;
            }
        }
        // B(0) prefetch into stage 0
        {
            size_t goff = (size_t)(n0 + brow) * KTOT + 0 + ub * 8;
            uint32_t bh = sb + B_HI_OFF(0), bl = sb + B_LO_OFF(0);
            #pragma unroll
            for (int u = 0; u < 4; u++) {
                uint32_t d = swaddr(0, brow, (ub + u) * 16);
                cp16(bh + d, g_Bt_hi + goff + u * 8);
                cp16(bl + d, g_Bt_lo + goff + u * 8);
            }
            CP_COMMIT();
        }

        int gg = 0, ib = 0, s = 0;
        for (int c = 0; c < NCHUNK; c++) {
            const int sn  = (s + 1 == NSTAGE) ? 0 : s + 1;
            int ngg = gg + 1, nib = ib;
            if (ngg == 9) { ngg = 0; nib = ib + 1; }

            // ---- prefetch B(c+1) into stage sn ----
            if (c + 1 < NCHUNK) {
                if (c + 1 >= NSTAGE) bar_sync(BAR_EMPTY(sn));
                const int kk = (ngg < 8) ? (ngg * IN_DIM + nib * KC) : (4096 + nib * KC);
                size_t goff = (size_t)(n0 + brow) * KTOT + kk + ub * 8;
                uint32_t bh = sb + B_HI_OFF(sn), bl = sb + B_LO_OFF(sn);
                #pragma unroll
                for (int u = 0; u < 4; u++) {
                    uint32_t d = swaddr(0, brow, (ub + u) * 16);
                    cp16(bh + d, g_Bt_hi + goff + u * 8);
                    cp16(bl + d, g_Bt_lo + goff + u * 8);
                }
                CP_COMMIT();
            }

            // ---- A expansion for chunk c into stage s ----
            {
                const bool is_silu = (gg == 8);
                const float gv = is_silu ? 0.0f : __ldg(grid + gg);
                uint32_t ahb = sb + A_HI_OFF(s);
                uint32_t alb = sb + A_LO_OFF(s);
                #pragma unroll
                for (int c16 = 0; c16 < 4; c16++) {
                    uint32_t hw[4], lw[4];
                    #pragma unroll
                    for (int q = 0; q < 4; q++) {
                        float v0 = xs[c16 * 8 + 2 * q];
                        float v1 = xs[c16 * 8 + 2 * q + 1];
                        float e0, e1;
                        if (!is_silu) {
                            // exp(-((v-g)*1.75)^2) = 2^(-4.418254*(v-g)^2)
                            float d0 = v0 - gv, d1 = v1 - gv;
                            e0 = ex2f(-4.418254f * d0 * d0);
                            e1 = ex2f(-4.418254f * d1 * d1);
                        } else {
                            // silu(v) = v / (1 + 2^(-1.442695*v))
                            e0 = v0 * rcpf(1.0f + ex2f(-1.442695f * v0));
                            e1 = v1 * rcpf(1.0f + ex2f(-1.442695f * v1));
                        }
                        uint32_t b0 = __float_as_uint(e0);
                        uint32_t b1 = __float_as_uint(e1);
                        hw[q] = __byte_perm(b0, b1, 0x7632);
                        float l0 = e0 - __uint_as_float(b0 & 0xFFFF0000u);
                        float l1 = e1 - __uint_as_float(b1 & 0xFFFF0000u);
                        lw[q] = cvt_bf16x2(l1, l0);
                    }
                    uint32_t d = swaddr(0, arow, half * 64 + c16 * 16);
                    sts128(ahb + d, make_uint4(hw[0], hw[1], hw[2], hw[3]));
                    sts128(alb + d, make_uint4(lw[0], lw[1], lw[2], lw[3]));
                }
            }

            // ---- prefetch x for next ib right after silu consumed old xs ----
            if (gg == 8 && nib < 8) {
                const float4* xp = reinterpret_cast<const float4*>(
                    x + (size_t)(row0 + arow) * IN_DIM + nib * KC + half * 32);
                #pragma unroll
                for (int j = 0; j < 8; j++) {
                    float4 v = xp[j];
                    xs[4 * j] = v.x; xs[4 * j + 1] = v.y;
                    xs[4 * j + 2] = v.z; xs[4 * j + 3] = v.w;
                }
            }

            // B(c) completed: one newer group (B(c+1)) may still be in flight
            if (c + 1 < NCHUNK) CP_WAIT1(); else CP_WAIT0();
            bar_arrive(BAR_FULL(s));

            gg = ngg; ib = nib; s = sn;
        }
    } else {
        // ================= CONSUMER (threads 256..511) =================
        const int wc = wid - 8;
        const int wm = wc & 3;
        const int wn = wc >> 2;

        float acc[2][8][4];
        #pragma unroll
        for (int mt = 0; mt < 2; mt++)
            #pragma unroll
            for (int nt = 0; nt < 8; nt++)
                #pragma unroll
                for (int q = 0; q < 4; q++) acc[mt][nt][q] = 0.0f;

        const int bno   = (lid & 7) + ((lid >> 4) << 3);
        const int bcsel = ((lid >> 3) & 1) << 4;
        const int arow  = lid & 15;
        const int acsel = (lid >> 4) << 4;

        int s = 0;
        for (int c = 0; c < NCHUNK; c++) {
            bar_sync(BAR_FULL(s));

            const uint32_t Ah = sb + A_HI_OFF(s), Al = sb + A_LO_OFF(s);
            const uint32_t Bh = sb + B_HI_OFF(s), Bl = sb + B_LO_OFF(s);
            #pragma unroll
            for (int ks = 0; ks < 4; ks++) {
                const int acolb = ks * 32 + acsel;
                uint32_t ahf[2][4], alf[2][4];
                #pragma unroll
                for (int mt = 0; mt < 2; mt++) {
                    int row = wm * 32 + mt * 16 + arow;
                    ldsm4(ahf[mt], swaddr(Ah, row, acolb));
                    ldsm4(alf[mt], swaddr(Al, row, acolb));
                }
                const int bcolb = ks * 32 + bcsel;
                #pragma unroll
                for (int p = 0; p < 4; p++) {
                    uint32_t bh4[4], bl4[4];
                    int brow = wn * 64 + p * 16 + bno;
                    ldsm4(bh4, swaddr(Bh, brow, bcolb));
                    ldsm4(bl4, swaddr(Bl, brow, bcolb));
                    #pragma unroll
                    for (int mt = 0; mt < 2; mt++) {
                        #pragma unroll
                        for (int j = 0; j < 2; j++) {
                            const int nt = p * 2 + j;
                            mma16816(acc[mt][nt], ahf[mt], bh4[j * 2], bh4[j * 2 + 1]);
                            mma16816(acc[mt][nt], ahf[mt], bl4[j * 2], bl4[j * 2 + 1]);
                            mma16816(acc[mt][nt], alf[mt], bh4[j * 2], bh4[j * 2 + 1]);
                        }
                    }
                }
            }

            bar_arrive(BAR_EMPTY(s));
            if (++s == NSTAGE) s = 0;
        }

        // ---- epilogue: bias + store ----
        #pragma unroll
        for (int mt = 0; mt < 2; mt++) {
            int row = row0 + wm * 32 + mt * 16 + (lid >> 2);
            #pragma unroll
            for (int nt = 0; nt < 8; nt++) {
                int col = n0 + wn * 64 + nt * 8 + (lid & 3) * 2;
                float2 bv = *reinterpret_cast<const float2*>(bb + col);
                float2 o0, o1;
                o0.x = acc[mt][nt][0] + bv.x;
                o0.y = acc[mt][nt][1] + bv.y;
                o1.x = acc[mt][nt][2] + bv.x;
                o1.y = acc[mt][nt][3] + bv.y;
                *reinterpret_cast<float2*>(out + (size_t)row * OUT_DIM + col) = o0;
                *reinterpret_cast<float2*>(out + (size_t)(row + 8) * OUT_DIM + col) = o1;
            }
        }
    }
}

// ---------------- launch ----------------
extern "C" void kernel_launch(void* const* d_in, const int* in_sizes, int n_in,
                              void* d_out, int out_size) {
    const float* x    = (const float*)d_in[0];
    const float* grid = (const float*)d_in[1];
    const float* sw   = (const float*)d_in[2];
    const float* bw   = (const float*)d_in[3];
    const float* bb   = (const float*)d_in[4];
    float* out = (float*)d_out;

    convert_b_kernel<<<dim3(16, 16, 9), dim3(32, 8)>>>(sw, bw);

    cudaFuncSetAttribute(kan_mma_kernel, cudaFuncAttributeMaxDynamicSharedMemorySize,
                         SMEM_TOTAL);
    dim3 g(OUT_DIM / BN, N_ROWS / BM);   // (4, 128) = 512 CTAs
    kan_mma_kernel<<<g, NTHREADS, SMEM_TOTAL>>>(x, grid, bb, out);
}